// round 6
// baseline (speedup 1.0000x reference)
#include <cuda_runtime.h>
#include <cuda_bf16.h>
#include <cstdint>

// ChaosModulator: per-channel nonlinear recurrence over t.
//   sigma = 3.5*z*(1-z) + 0.5*x
//   z'    = 0.5*z + 0.5*sigmoid(2*sigma)     (clip(0,1) is a provable no-op)
//   u     = 0.5*x + (z' - 0.5)
//
// Structure: contraction chunking (S=8 chunks of 512, WARM=96 from z=0.5)
// + cp.async double-buffered smem pipeline. Tile t+1 is prefetched via
// LDGSTS into the idle buffer while tile t is computed in place and stored,
// so DRAM stays busy through the compute phase. float4 XOR swizzle
// (c4 ^= row&7, 128B row stride) keeps cp.async 16B-aligned and makes
// LDS.128/STS.128 conflict-free. 2 barriers per 32-step tile.

#define CHUNK 512
#define WARM  96
#define TS    32
#define NT    (CHUNK / TS)   // 16 tiles

__device__ __forceinline__ float ex2_approx(float v) {
    float y; asm("ex2.approx.f32 %0, %1;" : "=f"(y) : "f"(v)); return y;
}
__device__ __forceinline__ float rcp_approx(float v) {
    float y; asm("rcp.approx.f32 %0, %1;" : "=f"(y) : "f"(v)); return y;
}

// sigma_tilde = -2*log2(e)*sigma = K1*(z - z^2) + K2*x
#define K1 (-10.098865286222744f)  /* -7 * log2(e) */
#define K2 (-1.4426950408889634f)  /* -1 * log2(e) */

__device__ __forceinline__ float step_z(float z, float xx) {
    float p  = fmaf(-z, z, z);          // z - z^2
    float tt = fmaf(K1, p, K2 * xx);
    float e  = ex2_approx(tt);
    float r  = rcp_approx(1.0f + e);    // sigmoid(2*sigma)
    return fmaf(0.5f, r, 0.5f * z);
}

__device__ __forceinline__ void cpasync16(uint32_t s, const void* g) {
    asm volatile("cp.async.cg.shared.global [%0], [%1], 16;"
                 :: "r"(s), "l"(g));
}
#define CP_COMMIT() asm volatile("cp.async.commit_group;" ::: "memory")
#define CP_WAIT0()  asm volatile("cp.async.wait_group 0;"  ::: "memory")

__global__ void __launch_bounds__(128, 7)
chaos_kernel(const float* __restrict__ x,
             const float* __restrict__ z0,
             float* __restrict__ u,
             int n_ch, int T)
{
    // [buffer][row*8 + swizzled c4], row stride = 32 floats = 128B
    __shared__ float4 buf[2][128 * 8];

    const int tid = threadIdx.x;
    const int ch0 = blockIdx.x * 16;

    // Loader/store role: thread covers rows r = a + 16j (j=0..7), col group c4.
    // r&7 (= chunk id of row) is constant = a&7 across j.
    const int a   = tid >> 3;           // 0..15
    const int c4  = tid & 7;
    const int sr  = a & 7;              // loader-side chunk id (swizzle key)

    // Compute role: thread owns row tid => channel ch0 + tid>>3, chunk tid&7.
    const int s   = tid & 7;
    const int ch  = ch0 + (tid >> 3);
    const int ckey = tid & 7;

    float z = (s == 0) ? z0[ch] : 0.5f;

    const size_t rowT = (size_t)T;
    const float* gx_l = x + (size_t)(ch0 + (a >> 3)) * rowT + sr * CHUNK + c4 * 4;
    float*       gu_l = u + (size_t)(ch0 + (a >> 3)) * rowT + sr * CHUNK + c4 * 4;

    const uint32_t sb0 = (uint32_t)__cvta_generic_to_shared(
        &buf[0][a * 8 + (c4 ^ sr)]);
    const uint32_t sb1 = (uint32_t)__cvta_generic_to_shared(
        &buf[1][a * 8 + (c4 ^ sr)]);
    // per-j stride in smem: 16 rows = 128 float4 = 2048 bytes

    // ---- Warmup: 3 tiles of 32 steps; rows/threads of chunk 0 skip ----
    for (int w = 0; w < WARM / TS; ++w) {
        if (sr != 0) {
            const float* g = gx_l - WARM + w * TS;
#pragma unroll
            for (int j = 0; j < 8; ++j)
                cpasync16(sb0 + j * 2048, g + (size_t)2 * j * rowT);
        }
        CP_COMMIT(); CP_WAIT0();
        __syncthreads();
        if (s != 0) {
#pragma unroll
            for (int c = 0; c < 8; ++c) {
                float4 v = buf[0][tid * 8 + (c ^ ckey)];
                z = step_z(z, v.x); z = step_z(z, v.y);
                z = step_z(z, v.z); z = step_z(z, v.w);
            }
        }
        __syncthreads();
    }

    // ---- Prologue: tile 0 -> buf0 ----
#pragma unroll
    for (int j = 0; j < 8; ++j)
        cpasync16(sb0 + j * 2048, gx_l + (size_t)2 * j * rowT);
    CP_COMMIT();

    // ---- Main pipeline ----
    for (int tile = 0; tile < NT; ++tile) {
        CP_WAIT0();
        __syncthreads();                 // tile data visible to all threads

        // Prefetch tile+1 into the other buffer (overlaps compute + store)
        if (tile + 1 < NT) {
            uint32_t sN = ((tile + 1) & 1) ? sb1 : sb0;
            const float* g = gx_l + (tile + 1) * TS;
#pragma unroll
            for (int j = 0; j < 8; ++j)
                cpasync16(sN + j * 2048, g + (size_t)2 * j * rowT);
            CP_COMMIT();
        }

        // Compute in place: x tile -> u tile
        {
            float4* bb = buf[tile & 1];
#pragma unroll
            for (int c = 0; c < 8; ++c) {
                int idx = tid * 8 + (c ^ ckey);
                float4 v = bb[idx];
                float4 o; float h;
                h = fmaf(0.5f, v.x, -0.5f); z = step_z(z, v.x); o.x = h + z;
                h = fmaf(0.5f, v.y, -0.5f); z = step_z(z, v.y); o.y = h + z;
                h = fmaf(0.5f, v.z, -0.5f); z = step_z(z, v.z); o.z = h + z;
                h = fmaf(0.5f, v.w, -0.5f); z = step_z(z, v.w); o.w = h + z;
                bb[idx] = o;
            }
        }
        __syncthreads();                 // u tile complete

        // Coalesced store-out
        {
            const float4* src = buf[tile & 1];
            float* gdst = gu_l + tile * TS;
#pragma unroll
            for (int j = 0; j < 8; ++j) {
                float4 v = src[a * 8 + (c4 ^ sr) + 128 * j];
                *(float4*)(gdst + (size_t)2 * j * rowT) = v;
            }
        }
    }
}

extern "C" void kernel_launch(void* const* d_in, const int* in_sizes, int n_in,
                              void* d_out, int out_size)
{
    const float* x  = (const float*)d_in[0];   // (b, c, t) f32
    const float* z0 = (const float*)d_in[1];   // (b, c)    f32
    float* u = (float*)d_out;

    int n_ch = in_sizes[1];            // b*c = 16384
    int T    = in_sizes[0] / n_ch;     // 4096

    int grid = n_ch / 16;              // 1024 blocks of 128 threads
    chaos_kernel<<<grid, 128>>>(x, z0, u, n_ch, T);
}

// round 9
// speedup vs baseline: 1.1377x; 1.1377x over previous
#include <cuda_runtime.h>
#include <cuda_bf16.h>
#include <cstdint>

// ChaosModulator: per-channel nonlinear recurrence over t.
//   sigma = 3.5*z*(1-z) + 0.5*x
//   z'    = 0.5*z + 0.5*sigmoid(2*sigma)     (clip(0,1) is a provable no-op)
//   u     = 0.5*x + (z' - 0.5)
//
// R7 structure: contraction chunking (S=8 chunks of 512, WARM=96 from z=0.5)
// + WARP-AUTONOMOUS 3-phase smem staging. R6 showed latency hiding comes from
// the number of independent streams per SM, and block-wide barriers collapse
// 4 warps into one stream. Now each warp owns 4 channels x 8 chunks = 32 rows
// (one contiguous 64KB span of x, since addr = row*CHUNK + t when T=8*CHUNK),
// stages 32-step tiles through its private 4KB smem slab, and syncs only via
// __syncwarp. Warps drift out of phase -> DRAM duty rises.
// XOR float4 swizzle (c4 ^ (row&7), 128B row stride): conflict-free STS/LDS.

#define WARM  96
#define TS    32

__device__ __forceinline__ float ex2_approx(float v) {
    float y; asm("ex2.approx.f32 %0, %1;" : "=f"(y) : "f"(v)); return y;
}
__device__ __forceinline__ float rcp_approx(float v) {
    float y; asm("rcp.approx.f32 %0, %1;" : "=f"(y) : "f"(v)); return y;
}

// sigma_tilde = -2*log2(e)*sigma = K1*(z - z^2) + K2*x
#define K1 (-10.098865286222744f)  /* -7 * log2(e) */
#define K2 (-1.4426950408889634f)  /* -1 * log2(e) */

__device__ __forceinline__ float step_z(float z, float xx) {
    float p  = fmaf(-z, z, z);          // z - z^2
    float tt = fmaf(K1, p, K2 * xx);
    float e  = ex2_approx(tt);
    float r  = rcp_approx(1.0f + e);    // sigmoid(2*sigma)
    return fmaf(0.5f, r, 0.5f * z);
}

__global__ void __launch_bounds__(128, 8)
chaos_kernel(const float* __restrict__ x,
             const float* __restrict__ z0,
             float* __restrict__ u,
             int n_ch, int T)
{
    // Per-warp slab: 32 rows x 8 float4 (128B row stride).
    __shared__ float4 sbuf[4][32][8];

    const int tid  = threadIdx.x;
    const int wid  = tid >> 5;
    const int lane = tid & 31;

    const int CHUNK = T >> 3;                 // 512 (S = 8 chunks)
    const int NT    = CHUNK / TS;             // 16 tiles

    // Warp owns channels [ch0, ch0+4): x span of 8*CHUNK*4 floats, contiguous.
    const int ch0 = blockIdx.x * 16 + wid * 4;
    const float* __restrict__ gx = x + (size_t)ch0 * T;
    float* __restrict__       gu = u + (size_t)ch0 * T;

    const int l3 = lane >> 3;                 // 0..3
    const int c4 = lane & 7;                  // float4 column group

    float4 (*sb)[8] = sbuf[wid];

    // Compute role: row = lane, channel = ch0 + (lane>>3), chunk s = lane&7.
    const int s    = lane & 7;
    const int ckey = lane & 7;
    float z = (s == 0) ? z0[ch0 + l3] : 0.5f;

    // ---- Warmup: 3 tiles of 32 steps (chunk-0 rows skip) ----
    for (int w = 0; w < WARM / TS; ++w) {
        const int t = -WARM + w * TS;
#pragma unroll
        for (int j = 0; j < 8; ++j) {
            int r   = l3 + 4 * j;             // row 0..31
            int key = r & 7;                  // chunk of this row
            if (key != 0) {
                float4 v = *(const float4*)(gx + (size_t)r * CHUNK + t + c4 * 4);
                sb[r][c4 ^ key] = v;
            }
        }
        __syncwarp();
        if (s != 0) {
#pragma unroll
            for (int c = 0; c < 8; ++c) {
                float4 v = sb[lane][c ^ ckey];
                z = step_z(z, v.x); z = step_z(z, v.y);
                z = step_z(z, v.z); z = step_z(z, v.w);
            }
        }
        __syncwarp();
    }

    // ---- Main: per-tile load -> compute in place -> store, warp-private ----
    for (int tile = 0; tile < NT; ++tile) {
        const int t = tile * TS;

#pragma unroll
        for (int j = 0; j < 8; ++j) {
            int r   = l3 + 4 * j;
            int key = r & 7;
            float4 v = *(const float4*)(gx + (size_t)r * CHUNK + t + c4 * 4);
            sb[r][c4 ^ key] = v;
        }
        __syncwarp();

#pragma unroll
        for (int c = 0; c < 8; ++c) {
            float4 v = sb[lane][c ^ ckey];
            float4 o; float h;
            h = fmaf(0.5f, v.x, -0.5f); z = step_z(z, v.x); o.x = h + z;
            h = fmaf(0.5f, v.y, -0.5f); z = step_z(z, v.y); o.y = h + z;
            h = fmaf(0.5f, v.z, -0.5f); z = step_z(z, v.z); o.z = h + z;
            h = fmaf(0.5f, v.w, -0.5f); z = step_z(z, v.w); o.w = h + z;
            sb[lane][c ^ ckey] = o;
        }
        __syncwarp();

#pragma unroll
        for (int j = 0; j < 8; ++j) {
            int r   = l3 + 4 * j;
            int key = r & 7;
            float4 v = sb[r][c4 ^ key];
            *(float4*)(gu + (size_t)r * CHUNK + t + c4 * 4) = v;
        }
        __syncwarp();                        // protect smem before next STS
    }
}

extern "C" void kernel_launch(void* const* d_in, const int* in_sizes, int n_in,
                              void* d_out, int out_size)
{
    const float* x  = (const float*)d_in[0];   // (b, c, t) f32
    const float* z0 = (const float*)d_in[1];   // (b, c)    f32
    float* u = (float*)d_out;

    int n_ch = in_sizes[1];            // b*c = 16384
    int T    = in_sizes[0] / n_ch;     // 4096

    int grid = n_ch / 16;              // 16 channels per 128-thread block
    chaos_kernel<<<grid, 128>>>(x, z0, u, n_ch, T);
}

// round 10
// speedup vs baseline: 1.2816x; 1.1265x over previous
#include <cuda_runtime.h>
#include <cuda_bf16.h>
#include <cstdint>

// ChaosModulator: per-channel nonlinear recurrence over t.
//   sigma = 3.5*z*(1-z) + 0.5*x
//   z'    = 0.5*z + 0.5*sigmoid(2*sigma)     (clip(0,1) is a provable no-op)
//   u     = 0.5*x + (z' - 0.5)
//
// R10: warp-autonomous 3-phase smem staging (R7) with
//   - occupancy push: __launch_bounds__(128,10) (51-reg target) + 32-bit
//     byte-offset addressing (one offset reg + 8KB constant stride instead
//     of 8 precomputed 64-bit pointers) -> more independent warp streams,
//     since DRAM duty has tracked occupancy ~1.5x in every round so far.
//   - WARM 96 -> 64: contraction residual at 64 steps is <=1e-6 pessimistic
//     (measured rel_err at W=96 was already pure-approx-error), saves 5.5%
//     of read traffic and a third of warmup compute.
// Each warp owns 4 channels x 8 chunks = 32 rows = one contiguous 64KB span
// of x (addr = row*CHUNK + t, T = 8*CHUNK). XOR float4 swizzle, __syncwarp only.

#define WARM  64
#define TS    32

__device__ __forceinline__ float ex2_approx(float v) {
    float y; asm("ex2.approx.f32 %0, %1;" : "=f"(y) : "f"(v)); return y;
}
__device__ __forceinline__ float rcp_approx(float v) {
    float y; asm("rcp.approx.f32 %0, %1;" : "=f"(y) : "f"(v)); return y;
}

// sigma_tilde = -2*log2(e)*sigma = K1*(z - z^2) + K2*x
#define K1 (-10.098865286222744f)  /* -7 * log2(e) */
#define K2 (-1.4426950408889634f)  /* -1 * log2(e) */

__device__ __forceinline__ float step_z(float z, float xx) {
    float p  = fmaf(-z, z, z);          // z - z^2
    float tt = fmaf(K1, p, K2 * xx);
    float e  = ex2_approx(tt);
    float r  = rcp_approx(1.0f + e);    // sigmoid(2*sigma)
    return fmaf(0.5f, r, 0.5f * z);
}

__global__ void __launch_bounds__(128, 10)
chaos_kernel(const float* __restrict__ x,
             const float* __restrict__ z0,
             float* __restrict__ u,
             int n_ch, int T)
{
    // Per-warp slab: 32 rows x 8 float4 (128B row stride).
    __shared__ float4 sbuf[4][32][8];

    const int tid  = threadIdx.x;
    const int wid  = tid >> 5;
    const int lane = tid & 31;

    const int CHUNK = T >> 3;                 // 512 (S = 8 chunks)
    const int NT    = CHUNK / TS;             // 16 tiles

    // Warp owns channels [ch0, ch0+4): one contiguous 64KB span of x.
    const int ch0 = blockIdx.x * 16 + wid * 4;
    const char* __restrict__ gx = (const char*)(x + (size_t)ch0 * T);
    char* __restrict__       gu = (char*)(u + (size_t)ch0 * T);

    const int l3 = lane >> 3;                 // 0..3  (row group)
    const int c4 = lane & 7;                  // float4 column group

    float4 (*sb)[8] = sbuf[wid];

    // Loader base byte-offset for row l3 (+ j*4 rows => + j*8192 bytes).
    const uint32_t off0 = (uint32_t)((l3 * CHUNK + c4 * 4) * 4);
    const uint32_t JSTR = (uint32_t)(4 * CHUNK * 4);   // 8192 for CHUNK=512

    // Compute role: row = lane, channel = ch0 + l3, chunk s = lane&7.
    const int s    = lane & 7;
    const int ckey = lane & 7;
    float z = (s == 0) ? z0[ch0 + l3] : 0.5f;

    // ---- Warmup: 2 tiles of 32 steps (chunk-0 rows skip) ----
    for (int w = 0; w < WARM / TS; ++w) {
        const int tb = (-WARM + w * TS) * 4;          // byte offset in t
        uint32_t off = off0;
#pragma unroll
        for (int j = 0; j < 8; ++j, off += JSTR) {
            int key = l3 | ((j & 1) << 2);            // (r&7) for r=l3+4j
            if (key != 0) {
                float4 v = *(const float4*)(gx + off + tb);
                sb[l3 + 4 * j][c4 ^ key] = v;
            }
        }
        __syncwarp();
        if (s != 0) {
#pragma unroll
            for (int c = 0; c < 8; ++c) {
                float4 v = sb[lane][c ^ ckey];
                z = step_z(z, v.x); z = step_z(z, v.y);
                z = step_z(z, v.z); z = step_z(z, v.w);
            }
        }
        __syncwarp();
    }

    // ---- Main: per-tile load -> compute in place -> store, warp-private ----
    for (int tile = 0; tile < NT; ++tile) {
        const uint32_t tb = (uint32_t)(tile * TS * 4);

        {
            uint32_t off = off0 + tb;
#pragma unroll
            for (int j = 0; j < 8; ++j, off += JSTR) {
                int key = l3 | ((j & 1) << 2);
                float4 v = *(const float4*)(gx + off);
                sb[l3 + 4 * j][c4 ^ key] = v;
            }
        }
        __syncwarp();

#pragma unroll
        for (int c = 0; c < 8; ++c) {
            float4 v = sb[lane][c ^ ckey];
            float4 o; float h;
            h = fmaf(0.5f, v.x, -0.5f); z = step_z(z, v.x); o.x = h + z;
            h = fmaf(0.5f, v.y, -0.5f); z = step_z(z, v.y); o.y = h + z;
            h = fmaf(0.5f, v.z, -0.5f); z = step_z(z, v.z); o.z = h + z;
            h = fmaf(0.5f, v.w, -0.5f); z = step_z(z, v.w); o.w = h + z;
            sb[lane][c ^ ckey] = o;
        }
        __syncwarp();

        {
            uint32_t off = off0 + tb;
#pragma unroll
            for (int j = 0; j < 8; ++j, off += JSTR) {
                int key = l3 | ((j & 1) << 2);
                float4 v = sb[l3 + 4 * j][c4 ^ key];
                *(float4*)(gu + off) = v;
            }
        }
        __syncwarp();                        // protect smem before next STS
    }
}

extern "C" void kernel_launch(void* const* d_in, const int* in_sizes, int n_in,
                              void* d_out, int out_size)
{
    const float* x  = (const float*)d_in[0];   // (b, c, t) f32
    const float* z0 = (const float*)d_in[1];   // (b, c)    f32
    float* u = (float*)d_out;

    int n_ch = in_sizes[1];            // b*c = 16384
    int T    = in_sizes[0] / n_ch;     // 4096

    int grid = n_ch / 16;              // 16 channels per 128-thread block
    chaos_kernel<<<grid, 128>>>(x, z0, u, n_ch, T);
}